// round 16
// baseline (speedup 1.0000x reference)
#include <cuda_runtime.h>
#include <cuda_fp16.h>
#include <cuda_bf16.h>

// Problem constants (GCN_55499567399154)
#define NMAX 50000
#define EMAX 800000
#define FIN  128
#define HID  128
#define NCLS 64

// ---------------- static scratch (no allocations allowed) ----------------
__device__ __align__(256) __half d_bufXh[NMAX * HID]; // activations (fp16)
__device__ __align__(256) __half d_bufG[NMAX * HID];  // g = dinv * (X @ W) (fp16)
__device__ __align__(256) __half d_Wh[3 * 16384 + 8192]; // fp16 weights
__device__ __align__(256) float  d_dinv[NMAX];
__device__ __align__(256) int    d_deg[NMAX];   // ZERO between calls (scan23 restores)
__device__ __align__(256) int    d_off[NMAX + 8];
__device__ __align__(256) int    d_cur[NMAX];
__device__ __align__(256) int    d_csr[EMAX];
__device__ __align__(256) int    d_bsum[512];

template <int N> struct Int { static constexpr int value = N; };

// ---------------- per-block edge-dtype detect (int64 vs int32 words) -------
// int64 little-endian: odd 32-bit words are high words == 0 (ids < 50000).
// Must be called by ALL threads of the block (contains __syncthreads_or).
__device__ __forceinline__ int block_detect_is64(const int* __restrict__ p, int E) {
    int cnt = (E < 256) ? E : 256;
    int bad = ((int)threadIdx.x < cnt) ? (p[2 * threadIdx.x + 1] != 0) : 0;
    return !__syncthreads_or(bad);
}

// ---------------- graph build ----------------
// 4 edges per thread, vectorized edge loads -> 4 independent atomics in
// flight (was 1 edge/thread at MLP=1, pure ATOMG latency).
__global__ void hist_kernel(const int* __restrict__ p, int E) {
    int is64 = block_detect_is64(p, E);
    int t = blockIdx.x * blockDim.x + threadIdx.x;
    int e0 = t * 4;
    if (e0 >= E) return;
    if (e0 + 4 <= E) {
        int c[4];
        if (is64) {
            uint4 a = *(const uint4*)(p + 2 * (size_t)(E + e0));
            uint4 b = *(const uint4*)(p + 2 * (size_t)(E + e0) + 4);
            c[0] = (int)a.x; c[1] = (int)a.z; c[2] = (int)b.x; c[3] = (int)b.z;
        } else {
            uint4 a = *(const uint4*)(p + (size_t)E + e0);
            c[0] = (int)a.x; c[1] = (int)a.y; c[2] = (int)a.z; c[3] = (int)a.w;
        }
#pragma unroll
        for (int i = 0; i < 4; i++) atomicAdd(&d_deg[c[i]], 1);
    } else {
        for (int e = e0; e < E; e++) {
            int c = is64 ? p[2 * (size_t)(E + e)] : p[(size_t)E + e];
            atomicAdd(&d_deg[c], 1);
        }
    }
}

// block-local exclusive scan of counts -> d_off (local), block totals -> d_bsum
__global__ void scan1_kernel(int n) {
    __shared__ int sh[512];
    int tid = threadIdx.x;
    int i = blockIdx.x * 512 + tid;
    int v = (i < n) ? d_deg[i] : 0;   // in-edge count (self-loop NOT in CSR)
    sh[tid] = v;
    __syncthreads();
#pragma unroll
    for (int dlt = 1; dlt < 512; dlt <<= 1) {
        int t = (tid >= dlt) ? sh[tid - dlt] : 0;
        __syncthreads();
        sh[tid] += t;
        __syncthreads();
    }
    if (i < n) d_off[i] = sh[tid] - v;            // block-local exclusive
    if (tid == 511) d_bsum[blockIdx.x] = sh[511]; // block total
}

// fused scan2+scan3: each block re-derives its prefix base by reducing
// d_bsum[0..b-1] (<=98 ints) in smem; finalizes off/cur/dinv; re-zeros deg.
__global__ void __launch_bounds__(512) scan23_kernel(int n, int nb) {
    __shared__ int red[128];
    int tid = threadIdx.x;
    int b = blockIdx.x;
    if (tid < 128) red[tid] = (tid < b) ? d_bsum[tid] : 0;
    __syncthreads();
#pragma unroll
    for (int d = 64; d > 0; d >>= 1) {
        if (tid < d) red[tid] += red[tid + d];
        __syncthreads();
    }
    int base = red[0];
    int i = b * 512 + tid;
    if (i < n) {
        int o = base + d_off[i];
        d_off[i] = o;
        d_cur[i] = o;
        int c = d_deg[i];
        d_dinv[i] = rsqrtf((float)(c + 1));  // +1 self-loop
        d_deg[i] = 0;                        // restore zero invariant for replay
    }
    if (b == nb - 1 && tid == 0) d_off[n] = base + d_bsum[b];  // = E
}

// 4 edges per thread, vectorized src+dst loads
__global__ void fill_kernel(const int* __restrict__ p, int E) {
    int is64 = block_detect_is64(p, E);
    int t = blockIdx.x * blockDim.x + threadIdx.x;
    int e0 = t * 4;
    if (e0 >= E) return;
    if (e0 + 4 <= E) {
        int c[4], s[4];
        if (is64) {
            uint4 a = *(const uint4*)(p + 2 * (size_t)(E + e0));
            uint4 b = *(const uint4*)(p + 2 * (size_t)(E + e0) + 4);
            uint4 u = *(const uint4*)(p + 2 * (size_t)e0);
            uint4 v = *(const uint4*)(p + 2 * (size_t)e0 + 4);
            c[0] = (int)a.x; c[1] = (int)a.z; c[2] = (int)b.x; c[3] = (int)b.z;
            s[0] = (int)u.x; s[1] = (int)u.z; s[2] = (int)v.x; s[3] = (int)v.z;
        } else {
            uint4 a = *(const uint4*)(p + (size_t)E + e0);
            uint4 u = *(const uint4*)(p + (size_t)e0);
            c[0] = (int)a.x; c[1] = (int)a.y; c[2] = (int)a.z; c[3] = (int)a.w;
            s[0] = (int)u.x; s[1] = (int)u.y; s[2] = (int)u.z; s[3] = (int)u.w;
        }
        int pos[4];
#pragma unroll
        for (int i = 0; i < 4; i++) pos[i] = atomicAdd(&d_cur[c[i]], 1);
#pragma unroll
        for (int i = 0; i < 4; i++) d_csr[pos[i]] = s[i];
    } else {
        for (int e = e0; e < E; e++) {
            int c = is64 ? p[2 * (size_t)(E + e)] : p[(size_t)E + e];
            int s = is64 ? p[2 * (size_t)e] : p[(size_t)e];
            int pos = atomicAdd(&d_cur[c], 1);
            d_csr[pos] = s;
        }
    }
}

// ---------------- fp16 weight conversion (all 4 in one launch) ----------------
// d_Wh layout: W1[0,16384) W2[16384,32768) W3[32768,49152) W4[49152,57344)
__global__ void conv_w_all_kernel(const float* __restrict__ W1, const float* __restrict__ W2,
                                  const float* __restrict__ W3, const float* __restrict__ W4) {
    int i = blockIdx.x * blockDim.x + threadIdx.x;  // half2 index, 28672 total
    if (i >= 28672) return;
    const float* src;
    if (i < 8192)       src = W1 + 2 * i;
    else if (i < 16384) src = W2 + 2 * i - 16384;
    else if (i < 24576) src = W3 + 2 * i - 32768;
    else                src = W4 + 2 * i - 49152;
    float2 v = *(const float2*)src;
    *(__half2*)(d_Wh + 2 * i) = __floats2half2_rn(v.x, v.y);
}

// ---------------- tensor-core GEMM: G = fp16( dinv .* (X @ Wh) ) ----------------
// FP32SRC: layer 1 reads fp32 X from the harness buffer, converts in smem store.
template <int NOUT, bool FP32SRC>
__global__ void __launch_bounds__(64 * (NOUT / 32)) gemm_tc_kernel(
    const float* __restrict__ X32, int woff, int n) {
    constexpr int K = 128;
    constexpr int BK = 64;
    constexpr int WN = NOUT / 32;
    constexpr int THREADS = 32 * 2 * WN;
    __shared__ __half Xs[128][BK + 8];
    __shared__ __half Ws[BK][NOUT + 8];

    const int tid = threadIdx.x;
    const int lane = tid & 31;
    const int wid = tid >> 5;
    const int wm = wid & 1;
    const int wn = wid >> 1;
    const int row0 = blockIdx.x * 128;
    const int m0 = wm * 64;

    float d[4][4][4];
#pragma unroll
    for (int a = 0; a < 4; a++)
#pragma unroll
        for (int b = 0; b < 4; b++)
#pragma unroll
            for (int c = 0; c < 4; c++) d[a][b][c] = 0.f;

    const __half* Wg = d_Wh + woff;

    for (int kb = 0; kb < K; kb += BK) {
        if constexpr (FP32SRC) {
            // 128 rows x 64 floats = 2048 float4
#pragma unroll
            for (int it = 0; it < 2048 / THREADS; ++it) {
                int v = tid + it * THREADS;
                int r = v >> 4;           // 16 float4 per row
                int q = v & 15;
                float4 f = make_float4(0.f, 0.f, 0.f, 0.f);
                int gr = row0 + r;
                if (gr < n) f = *(const float4*)(X32 + (size_t)gr * K + kb + q * 4);
                __half2 h0 = __floats2half2_rn(f.x, f.y);
                __half2 h1 = __floats2half2_rn(f.z, f.w);
                *(uint2*)&Xs[r][q * 4] =
                    make_uint2(*(unsigned int*)&h0, *(unsigned int*)&h1);
            }
        } else {
            // 128 rows x 64 halves = 1024 uint4
#pragma unroll
            for (int it = 0; it < 1024 / THREADS; ++it) {
                int v = tid + it * THREADS;
                int r = v >> 3;
                int kq = v & 7;
                uint4 val = make_uint4(0u, 0u, 0u, 0u);
                int gr = row0 + r;
                if (gr < n)
                    val = *(const uint4*)(d_bufXh + (size_t)gr * K + kb + kq * 8);
                *(uint4*)&Xs[r][kq * 8] = val;
            }
        }
#pragma unroll
        for (int it = 0; it < (8 * NOUT) / THREADS; ++it) {
            int v = tid + it * THREADS;
            int k = v / (NOUT / 8);
            int c8 = v % (NOUT / 8);
            *(uint4*)&Ws[k][c8 * 8] =
                *(const uint4*)(Wg + (size_t)(kb + k) * NOUT + c8 * 8);
        }
        __syncthreads();

#pragma unroll
        for (int ks = 0; ks < BK / 16; ++ks) {
            int k0 = ks * 16;
            unsigned int a[4][4];
#pragma unroll
            for (int mt = 0; mt < 4; mt++) {
                const __half* ap = &Xs[m0 + mt * 16 + (lane & 15)][k0 + ((lane >> 4) << 3)];
                unsigned int addr = (unsigned int)__cvta_generic_to_shared(ap);
                asm volatile(
                    "ldmatrix.sync.aligned.m8n8.x4.shared.b16 {%0,%1,%2,%3}, [%4];\n"
                    : "=r"(a[mt][0]), "=r"(a[mt][1]), "=r"(a[mt][2]), "=r"(a[mt][3])
                    : "r"(addr));
            }
            unsigned int bb[4][2];
#pragma unroll
            for (int nt = 0; nt < 4; nt++) {
                const __half* bp = &Ws[k0 + (lane & 15)][wn * 32 + nt * 8];
                unsigned int addr = (unsigned int)__cvta_generic_to_shared(bp);
                asm volatile(
                    "ldmatrix.sync.aligned.m8n8.x2.trans.shared.b16 {%0,%1}, [%2];\n"
                    : "=r"(bb[nt][0]), "=r"(bb[nt][1])
                    : "r"(addr));
            }
#pragma unroll
            for (int mt = 0; mt < 4; mt++)
#pragma unroll
                for (int nt = 0; nt < 4; nt++) {
                    asm volatile(
                        "mma.sync.aligned.m16n8k16.row.col.f32.f16.f16.f32 "
                        "{%0,%1,%2,%3}, {%4,%5,%6,%7}, {%8,%9}, {%0,%1,%2,%3};\n"
                        : "+f"(d[mt][nt][0]), "+f"(d[mt][nt][1]),
                          "+f"(d[mt][nt][2]), "+f"(d[mt][nt][3])
                        : "r"(a[mt][0]), "r"(a[mt][1]), "r"(a[mt][2]), "r"(a[mt][3]),
                          "r"(bb[nt][0]), "r"(bb[nt][1]));
                }
        }
        __syncthreads();
    }

    const int gr = lane >> 2;
    const int tg = lane & 3;
#pragma unroll
    for (int mt = 0; mt < 4; mt++) {
        int r_a = row0 + m0 + mt * 16 + gr;
        int r_b = r_a + 8;
#pragma unroll
        for (int nt = 0; nt < 4; nt++) {
            int col = wn * 32 + nt * 8 + 2 * tg;
            if (r_a < n) {
                float dv = d_dinv[r_a];
                *(__half2*)(d_bufG + (size_t)r_a * NOUT + col) =
                    __floats2half2_rn(d[mt][nt][0] * dv, d[mt][nt][1] * dv);
            }
            if (r_b < n) {
                float dv = d_dinv[r_b];
                *(__half2*)(d_bufG + (size_t)r_b * NOUT + col) =
                    __floats2half2_rn(d[mt][nt][2] * dv, d[mt][nt][3] * dv);
            }
        }
    }
}

// ---------------- aggregation: Y[c] = relu?(dinv[c]*(sum_in g + g[c]) + b) ----------------
// Pair-gather halves + coalesced index fetch (Round-10/12 winner, unchanged).
template <int F, bool RELU, bool OUT_PARAM>
__global__ void __launch_bounds__(256) agg_kernel(
    const float* __restrict__ bias, float* __restrict__ Yparam, int n) {
    constexpr int C = F / 16;  // features per lane (8 or 4)
    int gw = (blockIdx.x * 256 + threadIdx.x) >> 5;
    int lane = threadIdx.x & 31;
    int hf = lane >> 4;
    int hl = lane & 15;
    if (gw >= n) return;

    const __half* gbase = d_bufG;
    float acc[C];
#pragma unroll
    for (int i = 0; i < C; i++) acc[i] = 0.f;

    auto addv = [&](const unsigned int* w) {
#pragma unroll
        for (int j = 0; j < C / 2; j++) {
            float2 f = __half22float2(*(const __half2*)&w[j]);
            acc[2 * j] += f.x;
            acc[2 * j + 1] += f.y;
        }
    };
    auto loadrow = [&](int r) {
        if constexpr (C == 8) {
            uint4 v = *(const uint4*)(gbase + (size_t)r * F + hl * 8);
            addv((const unsigned int*)&v);
        } else {
            uint2 v = *(const uint2*)(gbase + (size_t)r * F + hl * 4);
            addv((const unsigned int*)&v);
        }
    };

    if (hf == 0) loadrow(gw);  // self contribution (once)

    int s = d_off[gw];
    int e = d_off[gw + 1];

    for (int base = s; base < e; base += 32) {
        int cnt = e - base;
        if (cnt > 32) cnt = 32;
        int idx = (lane < cnt) ? d_csr[base + lane] : 0;
        int k = 0;

        auto pairs = [&](auto npc) {
            constexpr int P = decltype(npc)::value;
            int r[P];
#pragma unroll
            for (int i = 0; i < P; i++)
                r[i] = __shfl_sync(0xffffffffu, idx, k + 2 * i + hf);
            if constexpr (C == 8) {
                uint4 v[P];
#pragma unroll
                for (int i = 0; i < P; i++)
                    v[i] = *(const uint4*)(gbase + (size_t)r[i] * F + hl * 8);
#pragma unroll
                for (int i = 0; i < P; i++) addv((const unsigned int*)&v[i]);
            } else {
                uint2 v[P];
#pragma unroll
                for (int i = 0; i < P; i++)
                    v[i] = *(const uint2*)(gbase + (size_t)r[i] * F + hl * 4);
#pragma unroll
                for (int i = 0; i < P; i++) addv((const unsigned int*)&v[i]);
            }
            k += 2 * P;
        };

        while (k + 15 < cnt) pairs(Int<8>{});
        if (k + 7 < cnt) pairs(Int<4>{});
        if (k + 3 < cnt) pairs(Int<2>{});
        if (k + 1 < cnt) pairs(Int<1>{});
        if (k < cnt) {
            int r = __shfl_sync(0xffffffffu, idx, k);
            if (hf == 0) loadrow(r);
        }
    }

#pragma unroll
    for (int i = 0; i < C; i++)
        acc[i] += __shfl_xor_sync(0xffffffffu, acc[i], 16);

    float dv = d_dinv[gw];
    float o[C];
    {
        float4 b0 = *(const float4*)(bias + hl * C);
        o[0] = dv * acc[0] + b0.x;
        o[1] = dv * acc[1] + b0.y;
        o[2] = dv * acc[2] + b0.z;
        o[3] = dv * acc[3] + b0.w;
        if constexpr (C == 8) {
            float4 b1 = *(const float4*)(bias + hl * C + 4);
            o[4] = dv * acc[4] + b1.x;
            o[5] = dv * acc[5] + b1.y;
            o[6] = dv * acc[6] + b1.z;
            o[7] = dv * acc[7] + b1.w;
        }
    }
    if (RELU) {
#pragma unroll
        for (int i = 0; i < C; i++) o[i] = fmaxf(o[i], 0.f);
    }

    if (hf == 0) {
        if constexpr (OUT_PARAM) {
            float* dst = Yparam + (size_t)gw * F + hl * C;
#pragma unroll
            for (int q = 0; q < C / 4; q++)
                *(float4*)(dst + 4 * q) =
                    make_float4(o[4 * q], o[4 * q + 1], o[4 * q + 2], o[4 * q + 3]);
        } else {
            __half* dst = d_bufXh + (size_t)gw * F + hl * C;
            unsigned int h[C / 2];
#pragma unroll
            for (int j = 0; j < C / 2; j++) {
                __half2 p = __floats2half2_rn(o[2 * j], o[2 * j + 1]);
                h[j] = *(unsigned int*)&p;
            }
            if constexpr (C == 8)
                *(uint4*)dst = make_uint4(h[0], h[1], h[2], h[3]);
            else
                *(uint2*)dst = make_uint2(h[0], h[1]);
        }
    }
}

// ---------------- launch ----------------
extern "C" void kernel_launch(void* const* d_in, const int* in_sizes, int n_in,
                              void* d_out, int out_size) {
    const float* x  = (const float*)d_in[0];
    const int*   ei = (const int*)d_in[1];   // int32 or int64 words; detected per block
    const float* W1 = (const float*)d_in[2];
    const float* b1 = (const float*)d_in[3];
    const float* W2 = (const float*)d_in[4];
    const float* b2 = (const float*)d_in[5];
    const float* W3 = (const float*)d_in[6];
    const float* b3 = (const float*)d_in[7];
    const float* W4 = (const float*)d_in[8];
    const float* b4 = (const float*)d_in[9];
    float* out = (float*)d_out;

    int n = in_sizes[0] / FIN;
    int E = in_sizes[1] / 2;

    // graph build: 4 launches (hist, scan1, scan23, fill); hist/fill do 4 edges/thread
    int edge_blocks = ((E + 3) / 4 + 255) / 256;
    hist_kernel<<<edge_blocks, 256>>>(ei, E);
    int nb = (n + 511) / 512;
    scan1_kernel<<<nb, 512>>>(n);
    scan23_kernel<<<nb, 512>>>(n, nb);
    fill_kernel<<<edge_blocks, 256>>>(ei, E);

    // weights fp16 (1 launch)
    conv_w_all_kernel<<<112, 256>>>(W1, W2, W3, W4);

    int gemm_blocks = (n + 127) / 128;
    int agg_blocks = (n * 32 + 255) / 256;

    // layer 1: fp32 X fused into GEMM (no separate conv_x kernel)
    gemm_tc_kernel<128, true><<<gemm_blocks, 256>>>(x, 0, n);
    agg_kernel<128, true, false><<<agg_blocks, 256>>>(b1, nullptr, n);
    // layer 2
    gemm_tc_kernel<128, false><<<gemm_blocks, 256>>>(nullptr, 16384, n);
    agg_kernel<128, true, false><<<agg_blocks, 256>>>(b2, nullptr, n);
    // layer 3
    gemm_tc_kernel<128, false><<<gemm_blocks, 256>>>(nullptr, 32768, n);
    agg_kernel<128, true, false><<<agg_blocks, 256>>>(b3, nullptr, n);
    // layer 4 (OUT=64) -> d_out
    gemm_tc_kernel<64, false><<<gemm_blocks, 128>>>(nullptr, 49152, n);
    agg_kernel<64, false, true><<<agg_blocks, 256>>>(b4, out, n);
}

// round 17
// speedup vs baseline: 1.0162x; 1.0162x over previous
#include <cuda_runtime.h>
#include <cuda_fp16.h>
#include <cuda_bf16.h>

// Problem constants (GCN_55499567399154)
#define NMAX 50000
#define EMAX 800000
#define FIN  128
#define HID  128
#define NCLS 64

// ---------------- static scratch (no allocations allowed) ----------------
__device__ __align__(256) __half d_bufXh[NMAX * HID]; // activations (fp16)
__device__ __align__(256) __half d_bufG[NMAX * HID];  // g = dinv * (X @ W) (fp16)
__device__ __align__(256) __half d_Wh[3 * 16384 + 8192]; // fp16 weights
__device__ __align__(256) float  d_dinv[NMAX];
__device__ __align__(256) int    d_deg[NMAX];   // ZERO between calls (scan23 restores)
__device__ __align__(256) int    d_off[NMAX + 8];
__device__ __align__(256) int    d_cur[NMAX];
__device__ __align__(256) int    d_csr[EMAX];
__device__ __align__(256) int    d_bsum[512];

template <int N> struct Int { static constexpr int value = N; };

// ---------------- per-block edge-dtype detect (int64 vs int32 words) -------
__device__ __forceinline__ int block_detect_is64(const int* __restrict__ p, int E) {
    int cnt = (E < 256) ? E : 256;
    int bad = ((int)threadIdx.x < cnt) ? (p[2 * threadIdx.x + 1] != 0) : 0;
    return !__syncthreads_or(bad);
}

// ---------------- graph build ----------------
__global__ void hist_kernel(const int* __restrict__ p, int E) {
    int is64 = block_detect_is64(p, E);
    int e = blockIdx.x * blockDim.x + threadIdx.x;
    if (e < E) {
        int c = is64 ? p[2 * (size_t)(E + e)] : p[(size_t)E + e];
        atomicAdd(&d_deg[c], 1);
    }
}

__global__ void scan1_kernel(int n) {
    __shared__ int sh[512];
    int tid = threadIdx.x;
    int i = blockIdx.x * 512 + tid;
    int v = (i < n) ? d_deg[i] : 0;
    sh[tid] = v;
    __syncthreads();
#pragma unroll
    for (int dlt = 1; dlt < 512; dlt <<= 1) {
        int t = (tid >= dlt) ? sh[tid - dlt] : 0;
        __syncthreads();
        sh[tid] += t;
        __syncthreads();
    }
    if (i < n) d_off[i] = sh[tid] - v;
    if (tid == 511) d_bsum[blockIdx.x] = sh[511];
}

__global__ void __launch_bounds__(512) scan23_kernel(int n, int nb) {
    __shared__ int red[128];
    int tid = threadIdx.x;
    int b = blockIdx.x;
    if (tid < 128) red[tid] = (tid < b) ? d_bsum[tid] : 0;
    __syncthreads();
#pragma unroll
    for (int d = 64; d > 0; d >>= 1) {
        if (tid < d) red[tid] += red[tid + d];
        __syncthreads();
    }
    int base = red[0];
    int i = b * 512 + tid;
    if (i < n) {
        int o = base + d_off[i];
        d_off[i] = o;
        d_cur[i] = o;
        int c = d_deg[i];
        d_dinv[i] = rsqrtf((float)(c + 1));  // +1 self-loop
        d_deg[i] = 0;                        // restore zero invariant for replay
    }
    if (b == nb - 1 && tid == 0) d_off[n] = base + d_bsum[b];
}

__global__ void fill_kernel(const int* __restrict__ p, int E) {
    int is64 = block_detect_is64(p, E);
    int e = blockIdx.x * blockDim.x + threadIdx.x;
    if (e < E) {
        int c = is64 ? p[2 * (size_t)(E + e)] : p[(size_t)E + e];
        int s = is64 ? p[2 * (size_t)e] : p[(size_t)e];
        int pos = atomicAdd(&d_cur[c], 1);
        d_csr[pos] = s;
    }
}

// ---------------- fp16 weight conversion (all 4 in one launch) ----------------
__global__ void conv_w_all_kernel(const float* __restrict__ W1, const float* __restrict__ W2,
                                  const float* __restrict__ W3, const float* __restrict__ W4) {
    int i = blockIdx.x * blockDim.x + threadIdx.x;
    if (i >= 28672) return;
    const float* src;
    if (i < 8192)       src = W1 + 2 * i;
    else if (i < 16384) src = W2 + 2 * i - 16384;
    else if (i < 24576) src = W3 + 2 * i - 32768;
    else                src = W4 + 2 * i - 49152;
    float2 v = *(const float2*)src;
    *(__half2*)(d_Wh + 2 * i) = __floats2half2_rn(v.x, v.y);
}

// ---------------- tensor-core GEMM: G = fp16( dinv .* (X @ Wh) ) ----------------
template <int NOUT, bool FP32SRC>
__global__ void __launch_bounds__(64 * (NOUT / 32)) gemm_tc_kernel(
    const float* __restrict__ X32, int woff, int n) {
    constexpr int K = 128;
    constexpr int BK = 64;
    constexpr int WN = NOUT / 32;
    constexpr int THREADS = 32 * 2 * WN;
    __shared__ __half Xs[128][BK + 8];
    __shared__ __half Ws[BK][NOUT + 8];

    const int tid = threadIdx.x;
    const int lane = tid & 31;
    const int wid = tid >> 5;
    const int wm = wid & 1;
    const int wn = wid >> 1;
    const int row0 = blockIdx.x * 128;
    const int m0 = wm * 64;

    float d[4][4][4];
#pragma unroll
    for (int a = 0; a < 4; a++)
#pragma unroll
        for (int b = 0; b < 4; b++)
#pragma unroll
            for (int c = 0; c < 4; c++) d[a][b][c] = 0.f;

    const __half* Wg = d_Wh + woff;

    for (int kb = 0; kb < K; kb += BK) {
        if constexpr (FP32SRC) {
#pragma unroll
            for (int it = 0; it < 2048 / THREADS; ++it) {
                int v = tid + it * THREADS;
                int r = v >> 4;
                int q = v & 15;
                float4 f = make_float4(0.f, 0.f, 0.f, 0.f);
                int gr = row0 + r;
                if (gr < n) f = *(const float4*)(X32 + (size_t)gr * K + kb + q * 4);
                __half2 h0 = __floats2half2_rn(f.x, f.y);
                __half2 h1 = __floats2half2_rn(f.z, f.w);
                *(uint2*)&Xs[r][q * 4] =
                    make_uint2(*(unsigned int*)&h0, *(unsigned int*)&h1);
            }
        } else {
#pragma unroll
            for (int it = 0; it < 1024 / THREADS; ++it) {
                int v = tid + it * THREADS;
                int r = v >> 3;
                int kq = v & 7;
                uint4 val = make_uint4(0u, 0u, 0u, 0u);
                int gr = row0 + r;
                if (gr < n)
                    val = *(const uint4*)(d_bufXh + (size_t)gr * K + kb + kq * 8);
                *(uint4*)&Xs[r][kq * 8] = val;
            }
        }
#pragma unroll
        for (int it = 0; it < (8 * NOUT) / THREADS; ++it) {
            int v = tid + it * THREADS;
            int k = v / (NOUT / 8);
            int c8 = v % (NOUT / 8);
            *(uint4*)&Ws[k][c8 * 8] =
                *(const uint4*)(Wg + (size_t)(kb + k) * NOUT + c8 * 8);
        }
        __syncthreads();

#pragma unroll
        for (int ks = 0; ks < BK / 16; ++ks) {
            int k0 = ks * 16;
            unsigned int a[4][4];
#pragma unroll
            for (int mt = 0; mt < 4; mt++) {
                const __half* ap = &Xs[m0 + mt * 16 + (lane & 15)][k0 + ((lane >> 4) << 3)];
                unsigned int addr = (unsigned int)__cvta_generic_to_shared(ap);
                asm volatile(
                    "ldmatrix.sync.aligned.m8n8.x4.shared.b16 {%0,%1,%2,%3}, [%4];\n"
                    : "=r"(a[mt][0]), "=r"(a[mt][1]), "=r"(a[mt][2]), "=r"(a[mt][3])
                    : "r"(addr));
            }
            unsigned int bb[4][2];
#pragma unroll
            for (int nt = 0; nt < 4; nt++) {
                const __half* bp = &Ws[k0 + (lane & 15)][wn * 32 + nt * 8];
                unsigned int addr = (unsigned int)__cvta_generic_to_shared(bp);
                asm volatile(
                    "ldmatrix.sync.aligned.m8n8.x2.trans.shared.b16 {%0,%1}, [%2];\n"
                    : "=r"(bb[nt][0]), "=r"(bb[nt][1])
                    : "r"(addr));
            }
#pragma unroll
            for (int mt = 0; mt < 4; mt++)
#pragma unroll
                for (int nt = 0; nt < 4; nt++) {
                    asm volatile(
                        "mma.sync.aligned.m16n8k16.row.col.f32.f16.f16.f32 "
                        "{%0,%1,%2,%3}, {%4,%5,%6,%7}, {%8,%9}, {%0,%1,%2,%3};\n"
                        : "+f"(d[mt][nt][0]), "+f"(d[mt][nt][1]),
                          "+f"(d[mt][nt][2]), "+f"(d[mt][nt][3])
                        : "r"(a[mt][0]), "r"(a[mt][1]), "r"(a[mt][2]), "r"(a[mt][3]),
                          "r"(bb[nt][0]), "r"(bb[nt][1]));
                }
        }
        __syncthreads();
    }

    const int gr = lane >> 2;
    const int tg = lane & 3;
#pragma unroll
    for (int mt = 0; mt < 4; mt++) {
        int r_a = row0 + m0 + mt * 16 + gr;
        int r_b = r_a + 8;
#pragma unroll
        for (int nt = 0; nt < 4; nt++) {
            int col = wn * 32 + nt * 8 + 2 * tg;
            if (r_a < n) {
                float dv = d_dinv[r_a];
                *(__half2*)(d_bufG + (size_t)r_a * NOUT + col) =
                    __floats2half2_rn(d[mt][nt][0] * dv, d[mt][nt][1] * dv);
            }
            if (r_b < n) {
                float dv = d_dinv[r_b];
                *(__half2*)(d_bufG + (size_t)r_b * NOUT + col) =
                    __floats2half2_rn(d[mt][nt][2] * dv, d[mt][nt][3] * dv);
            }
        }
    }
}

// ---------------- aggregation (Round-10/12 winner, unchanged) ----------------
template <int F, bool RELU, bool OUT_PARAM>
__global__ void __launch_bounds__(256) agg_kernel(
    const float* __restrict__ bias, float* __restrict__ Yparam, int n) {
    constexpr int C = F / 16;
    int gw = (blockIdx.x * 256 + threadIdx.x) >> 5;
    int lane = threadIdx.x & 31;
    int hf = lane >> 4;
    int hl = lane & 15;
    if (gw >= n) return;

    const __half* gbase = d_bufG;
    float acc[C];
#pragma unroll
    for (int i = 0; i < C; i++) acc[i] = 0.f;

    auto addv = [&](const unsigned int* w) {
#pragma unroll
        for (int j = 0; j < C / 2; j++) {
            float2 f = __half22float2(*(const __half2*)&w[j]);
            acc[2 * j] += f.x;
            acc[2 * j + 1] += f.y;
        }
    };
    auto loadrow = [&](int r) {
        if constexpr (C == 8) {
            uint4 v = *(const uint4*)(gbase + (size_t)r * F + hl * 8);
            addv((const unsigned int*)&v);
        } else {
            uint2 v = *(const uint2*)(gbase + (size_t)r * F + hl * 4);
            addv((const unsigned int*)&v);
        }
    };

    if (hf == 0) loadrow(gw);

    int s = d_off[gw];
    int e = d_off[gw + 1];

    for (int base = s; base < e; base += 32) {
        int cnt = e - base;
        if (cnt > 32) cnt = 32;
        int idx = (lane < cnt) ? d_csr[base + lane] : 0;
        int k = 0;

        auto pairs = [&](auto npc) {
            constexpr int P = decltype(npc)::value;
            int r[P];
#pragma unroll
            for (int i = 0; i < P; i++)
                r[i] = __shfl_sync(0xffffffffu, idx, k + 2 * i + hf);
            if constexpr (C == 8) {
                uint4 v[P];
#pragma unroll
                for (int i = 0; i < P; i++)
                    v[i] = *(const uint4*)(gbase + (size_t)r[i] * F + hl * 8);
#pragma unroll
                for (int i = 0; i < P; i++) addv((const unsigned int*)&v[i]);
            } else {
                uint2 v[P];
#pragma unroll
                for (int i = 0; i < P; i++)
                    v[i] = *(const uint2*)(gbase + (size_t)r[i] * F + hl * 4);
#pragma unroll
                for (int i = 0; i < P; i++) addv((const unsigned int*)&v[i]);
            }
            k += 2 * P;
        };

        while (k + 15 < cnt) pairs(Int<8>{});
        if (k + 7 < cnt) pairs(Int<4>{});
        if (k + 3 < cnt) pairs(Int<2>{});
        if (k + 1 < cnt) pairs(Int<1>{});
        if (k < cnt) {
            int r = __shfl_sync(0xffffffffu, idx, k);
            if (hf == 0) loadrow(r);
        }
    }

#pragma unroll
    for (int i = 0; i < C; i++)
        acc[i] += __shfl_xor_sync(0xffffffffu, acc[i], 16);

    float dv = d_dinv[gw];
    float o[C];
    {
        float4 b0 = *(const float4*)(bias + hl * C);
        o[0] = dv * acc[0] + b0.x;
        o[1] = dv * acc[1] + b0.y;
        o[2] = dv * acc[2] + b0.z;
        o[3] = dv * acc[3] + b0.w;
        if constexpr (C == 8) {
            float4 b1 = *(const float4*)(bias + hl * C + 4);
            o[4] = dv * acc[4] + b1.x;
            o[5] = dv * acc[5] + b1.y;
            o[6] = dv * acc[6] + b1.z;
            o[7] = dv * acc[7] + b1.w;
        }
    }
    if (RELU) {
#pragma unroll
        for (int i = 0; i < C; i++) o[i] = fmaxf(o[i], 0.f);
    }

    if (hf == 0) {
        if constexpr (OUT_PARAM) {
            float* dst = Yparam + (size_t)gw * F + hl * C;
#pragma unroll
            for (int q = 0; q < C / 4; q++)
                *(float4*)(dst + 4 * q) =
                    make_float4(o[4 * q], o[4 * q + 1], o[4 * q + 2], o[4 * q + 3]);
        } else {
            __half* dst = d_bufXh + (size_t)gw * F + hl * C;
            unsigned int h[C / 2];
#pragma unroll
            for (int j = 0; j < C / 2; j++) {
                __half2 p = __floats2half2_rn(o[2 * j], o[2 * j + 1]);
                h[j] = *(unsigned int*)&p;
            }
            if constexpr (C == 8)
                *(uint4*)dst = make_uint4(h[0], h[1], h[2], h[3]);
            else
                *(uint2*)dst = make_uint2(h[0], h[1]);
        }
    }
}

// ---------------- launch (forked capture: build || conv_w+gemm1) ----------------
extern "C" void kernel_launch(void* const* d_in, const int* in_sizes, int n_in,
                              void* d_out, int out_size) {
    const float* x  = (const float*)d_in[0];
    const int*   ei = (const int*)d_in[1];
    const float* W1 = (const float*)d_in[2];
    const float* b1 = (const float*)d_in[3];
    const float* W2 = (const float*)d_in[4];
    const float* b2 = (const float*)d_in[5];
    const float* W3 = (const float*)d_in[6];
    const float* b3 = (const float*)d_in[7];
    const float* W4 = (const float*)d_in[8];
    const float* b4 = (const float*)d_in[9];
    float* out = (float*)d_out;

    int n = in_sizes[0] / FIN;
    int E = in_sizes[1] / 2;

    int nb = (n + 511) / 512;
    int gemm_blocks = (n + 127) / 128;
    int agg_blocks = (n * 32 + 255) / 256;

    // Side stream + events for forked graph capture. Created per call
    // (host-side objects, not device memory). NOT destroyed here: destroying
    // a stream that participated in an active capture invalidates it; the
    // few kernel_launch invocations leak a handful of handles, harmless.
    cudaStream_t s2 = 0;
    cudaEvent_t evFork = 0, evScan = 0, evJoin = 0;
    bool forked = (cudaStreamCreateWithFlags(&s2, cudaStreamNonBlocking) == cudaSuccess) &&
                  (cudaEventCreateWithFlags(&evFork, cudaEventDisableTiming) == cudaSuccess) &&
                  (cudaEventCreateWithFlags(&evScan, cudaEventDisableTiming) == cudaSuccess) &&
                  (cudaEventCreateWithFlags(&evJoin, cudaEventDisableTiming) == cudaSuccess);

    if (forked) {
        // fork: bring s2 into the capture
        cudaEventRecord(evFork, 0);
        cudaStreamWaitEvent(s2, evFork, 0);
        // side branch: weight conversion (independent)
        conv_w_all_kernel<<<112, 256, 0, s2>>>(W1, W2, W3, W4);
        // origin branch: graph build up to scan23 (produces dinv + cur)
        hist_kernel<<<(E + 255) / 256, 256>>>(ei, E);
        scan1_kernel<<<nb, 512>>>(n);
        scan23_kernel<<<nb, 512>>>(n, nb);
        cudaEventRecord(evScan, 0);
        // side branch: gemm1 needs dinv (scan23) + Wh (conv_w) + x
        cudaStreamWaitEvent(s2, evScan, 0);
        gemm_tc_kernel<128, true><<<gemm_blocks, 256, 0, s2>>>(x, 0, n);
        cudaEventRecord(evJoin, s2);
        // origin branch: fill runs concurrently with gemm1
        fill_kernel<<<(E + 255) / 256, 256>>>(ei, E);
        // join before agg1 (needs csr + bufG)
        cudaStreamWaitEvent(0, evJoin, 0);
    } else {
        // serial fallback (identical semantics)
        conv_w_all_kernel<<<112, 256>>>(W1, W2, W3, W4);
        hist_kernel<<<(E + 255) / 256, 256>>>(ei, E);
        scan1_kernel<<<nb, 512>>>(n);
        scan23_kernel<<<nb, 512>>>(n, nb);
        gemm_tc_kernel<128, true><<<gemm_blocks, 256>>>(x, 0, n);
        fill_kernel<<<(E + 255) / 256, 256>>>(ei, E);
    }

    agg_kernel<128, true, false><<<agg_blocks, 256>>>(b1, nullptr, n);
    // layer 2
    gemm_tc_kernel<128, false><<<gemm_blocks, 256>>>(nullptr, 16384, n);
    agg_kernel<128, true, false><<<agg_blocks, 256>>>(b2, nullptr, n);
    // layer 3
    gemm_tc_kernel<128, false><<<gemm_blocks, 256>>>(nullptr, 32768, n);
    agg_kernel<128, true, false><<<agg_blocks, 256>>>(b3, nullptr, n);
    // layer 4 (OUT=64) -> d_out
    gemm_tc_kernel<64, false><<<gemm_blocks, 128>>>(nullptr, 49152, n);
    agg_kernel<64, false, true><<<agg_blocks, 256>>>(b4, out, n);
}